// round 7
// baseline (speedup 1.0000x reference)
#include <cuda_runtime.h>
#include <math.h>
#include <stdint.h>

#define MAXN 50048
#define MAXE 800000

// ---------------- scratch (device globals; no allocation allowed) ----------
__device__ __align__(128) float g_h[MAXN * 256];
__device__ __align__(128) float g_skip[MAXN * 256];
__device__ __align__(128) float g_hw[MAXN * 256];
__device__ __align__(128) float g_p[MAXN * 256];
__device__ __align__(128) float g_f1[MAXN * 512];
__device__ __align__(128) float g_logits[MAXN * 64];
__device__ __align__(128) float g_dinv[MAXN];
__device__ __align__(128) int   g_degi[MAXN];
__device__ __align__(128) int   g_rowptr[MAXN + 1];
__device__ __align__(128) int   g_cursor[MAXN];
__device__ __align__(128) int   g_esrc[MAXE];
__device__ __align__(128) float g_enorm[MAXE];
__device__ __align__(128) float g_wt[524288];   // all transposed weights (2 MB)

// ---------------- helpers --------------------------------------------------
__device__ __forceinline__ float gelu_exact(float x) {
    return 0.5f * x * (1.0f + erff(x * 0.70710678118654752440f));
}
__device__ __forceinline__ void mma_tf32(float* c, const uint32_t* a, const uint32_t* b) {
    asm("mma.sync.aligned.m16n8k8.row.col.f32.tf32.tf32.f32 "
        "{%0,%1,%2,%3},{%4,%5,%6,%7},{%8,%9},{%0,%1,%2,%3};"
        : "+f"(c[0]), "+f"(c[1]), "+f"(c[2]), "+f"(c[3])
        : "r"(a[0]), "r"(a[1]), "r"(a[2]), "r"(a[3]), "r"(b[0]), "r"(b[1]));
}
__device__ __forceinline__ void ldsm_x4(uint32_t* r, uint32_t saddr) {
    asm volatile("ldmatrix.sync.aligned.m8n8.x4.shared.b16 {%0,%1,%2,%3}, [%4];"
                 : "=r"(r[0]), "=r"(r[1]), "=r"(r[2]), "=r"(r[3]) : "r"(saddr));
}
__device__ __forceinline__ void ldsm_x2(uint32_t* r, uint32_t saddr) {
    asm volatile("ldmatrix.sync.aligned.m8n8.x2.shared.b16 {%0,%1}, [%2];"
                 : "=r"(r[0]), "=r"(r[1]) : "r"(saddr));
}
__device__ __forceinline__ void cp16(void* dst, const void* src, int bytes) {
    uint32_t d = (uint32_t)__cvta_generic_to_shared(dst);
    asm volatile("cp.async.cg.shared.global [%0], [%1], 16, %2;"
                 :: "r"(d), "l"(src), "r"(bytes));
}
__device__ __forceinline__ void cp_commit() { asm volatile("cp.async.commit_group;"); }
template <int N>
__device__ __forceinline__ void cp_wait() { asm volatile("cp.async.wait_group %0;" :: "n"(N)); }

// ---------------- batched weight transpose: W[K][N] -> Wt[N][K] ------------
struct TransArgs {
    const float* W[9];
    long long    woff[9];   // offset into g_wt (floats)
    int K[9];
    int N[9];
};
__global__ void k_transpose_all(TransArgs a, float* wt) {
    __shared__ float tile[32][33];
    int m = blockIdx.z;
    int K = a.K[m], N = a.N[m];
    int k0 = blockIdx.x * 32, n0 = blockIdx.y * 32;
    if (k0 >= K || n0 >= N) return;
    const float* W = a.W[m];
    float* Wt = wt + a.woff[m];
    for (int i = threadIdx.y; i < 32; i += 8)
        tile[i][threadIdx.x] = W[(size_t)(k0 + i) * N + n0 + threadIdx.x];
    __syncthreads();
    for (int i = threadIdx.y; i < 32; i += 8)
        Wt[(size_t)(n0 + i) * K + k0 + threadIdx.x] = tile[threadIdx.x][i];
}

// ---------------- preprocessing: degree, fused scan+dinv, bucket -----------
__global__ void k_count(int* deg, const int* __restrict__ dst, int e) {
    int i = blockIdx.x * blockDim.x + threadIdx.x;
    if (i < e) atomicAdd(&deg[dst[i]], 1);
}
// single-block fused: prefix-sum of degrees -> rowptr/cursor, plus dinv
__global__ void __launch_bounds__(1024) k_scan_all(
    const int* __restrict__ deg, float* __restrict__ dinv,
    int* __restrict__ rowptr, int* __restrict__ cursor, int n, int e) {
    __shared__ int sh[1024];
    int t = threadIdx.x;
    int per = (n + 1023) >> 10;
    int lo = t * per, hi = min(lo + per, n);
    int sum = 0;
    for (int i = lo; i < hi; i++) sum += deg[i];
    sh[t] = sum;
    __syncthreads();
    for (int o = 1; o < 1024; o <<= 1) {
        int u = (t >= o) ? sh[t - o] : 0;
        __syncthreads();
        sh[t] += u;
        __syncthreads();
    }
    int off = sh[t] - sum;  // exclusive prefix for this thread's chunk
    for (int i = lo; i < hi; i++) {
        int d = deg[i];
        rowptr[i] = off;
        cursor[i] = off;
        dinv[i] = rsqrtf((float)d + 1.0f);
        off += d;
    }
    if (t == 0) rowptr[n] = e;
}
__global__ void k_bucket(const int* __restrict__ src, const int* __restrict__ dst,
                         const float* __restrict__ dinv, int* __restrict__ cursor,
                         int* __restrict__ esrc, float* __restrict__ enorm, int e) {
    int i = blockIdx.x * blockDim.x + threadIdx.x;
    if (i < e) {
        int s = src[i], d = dst[i];
        int pos = atomicAdd(&cursor[d], 1);
        esrc[pos] = s;
        enorm[pos] = dinv[s] * dinv[d];
    }
}

// ---------------- TF32 GEMM: ldmatrix fragments + 3-stage cp.async ---------
// C[M,N] = A[M,K] @ Wt^T where Wt is [N][K] (k-contiguous, pre-transposed).
// BM=128, BN=64, BK=32, STAGES=3; 8 warps (4 M x 2 N), warp tile 32x32.
// fp32 bits fed raw to HMMA.tf32 (RZ truncation).
// MODE: 0 = raw store, 1 = +bias+addmat, 2 = gelu(x+bias)
#define STAGES 3
#define A_PITCH 36
#define B_PITCH 36
#define A_STAGE (128 * A_PITCH)
#define B_STAGE (64 * B_PITCH)
#define SMEM_FLOATS (STAGES * (A_STAGE + B_STAGE))
#define SMEM_BYTES  (SMEM_FLOATS * 4)    // 82944

template <int MODE>
__global__ void __launch_bounds__(256) sgemm_tc(
    const float* __restrict__ A, const float* __restrict__ Bt, float* __restrict__ C,
    int M, int K, int N, const float* __restrict__ bias, const float* __restrict__ add) {
    extern __shared__ float smem[];
    const uint32_t smem_u32 = (uint32_t)__cvta_generic_to_shared(smem);

    const int tid  = threadIdx.x;
    const int lane = tid & 31;
    const int wid  = tid >> 5;
    const int wm = wid & 3, wn = wid >> 2;
    const int gid = lane >> 2, tig = lane & 3;
    const int row0 = blockIdx.y * 128;
    const int col0 = blockIdx.x * 64;

    // A tile loader coords: 1024 chunks of 16B -> 4 per thread
    const int ar[4] = {(tid + 0) >> 3, (tid + 256) >> 3, (tid + 512) >> 3, (tid + 768) >> 3};
    const int ak = (tid & 7) * 4;
    // B tile loader coords (Bt rows = n, 8 chunks/row): 512 chunks -> 2 per thread
    const int bn[2] = {(tid + 0) >> 3, (tid + 256) >> 3};
    const int bk = (tid & 7) * 4;

    const int k_tiles = K >> 5;

    auto load_stage = [&](int s, int k0) {
        float* as = smem + s * A_STAGE;
        float* bs = smem + STAGES * A_STAGE + s * B_STAGE;
        #pragma unroll
        for (int i = 0; i < 4; i++) {
            int row = ar[i];
            int grow = row0 + row;
            int ok = (grow < M) ? 16 : 0;
            if (!ok) grow = M - 1;
            cp16(&as[row * A_PITCH + ak], &A[(size_t)grow * K + k0 + ak], ok);
        }
        #pragma unroll
        for (int i = 0; i < 2; i++) {
            int n = bn[i];
            cp16(&bs[n * B_PITCH + bk], &Bt[(size_t)(col0 + n) * K + k0 + bk], 16);
        }
    };

    // ldmatrix per-lane byte offsets
    // A x4: tiles (rows r..r+7 / r+8..r+15) x (cols kb..+3 / kb+4..+7)
    const int a_i = lane & 7, a_t = lane >> 3;
    const uint32_t a_off = ((uint32_t)((wm * 32 + a_i + ((a_t & 1) << 3)) * A_PITCH
                                       + ((a_t >> 1) << 2))) * 4u;
    // B x2: tiles (rows n..n+7) x (cols kb..+3 / kb+4..+7); lanes 0-15 supply addrs
    const int b_i = lane & 7, b_t = (lane >> 3) & 1;
    const uint32_t b_off = ((uint32_t)((wn * 32 + b_i) * B_PITCH + (b_t << 2))) * 4u;

    float acc[2][4][4];
    #pragma unroll
    for (int i = 0; i < 2; i++)
        #pragma unroll
        for (int j = 0; j < 4; j++)
            #pragma unroll
            for (int k = 0; k < 4; k++) acc[i][j][k] = 0.0f;

    #pragma unroll
    for (int s = 0; s < STAGES - 1; s++) {
        if (s < k_tiles) load_stage(s, s * 32);
        cp_commit();
    }

    for (int t = 0; t < k_tiles; t++) {
        cp_wait<STAGES - 2>();
        __syncthreads();
        const int st = t % STAGES;
        const uint32_t as_base = smem_u32 + (uint32_t)(st * A_STAGE) * 4u;
        const uint32_t bs_base = smem_u32 + (uint32_t)(STAGES * A_STAGE + st * B_STAGE) * 4u;

        #pragma unroll
        for (int kb = 0; kb < 32; kb += 8) {
            uint32_t af[2][4], bf[4][2];
            #pragma unroll
            for (int mt = 0; mt < 2; mt++)
                ldsm_x4(af[mt], as_base + a_off + (uint32_t)(mt * 16 * A_PITCH + kb) * 4u);
            #pragma unroll
            for (int nt = 0; nt < 4; nt++)
                ldsm_x2(bf[nt], bs_base + b_off + (uint32_t)(nt * 8 * B_PITCH + kb) * 4u);
            #pragma unroll
            for (int mt = 0; mt < 2; mt++)
                #pragma unroll
                for (int nt = 0; nt < 4; nt++)
                    mma_tf32(acc[mt][nt], af[mt], bf[nt]);
        }

        int nt2 = t + STAGES - 1;
        if (nt2 < k_tiles) load_stage(nt2 % STAGES, nt2 * 32);
        cp_commit();
    }

    // epilogue
    #pragma unroll
    for (int mt = 0; mt < 2; mt++) {
        #pragma unroll
        for (int half = 0; half < 2; half++) {
            int row = row0 + wm * 32 + mt * 16 + gid + half * 8;
            if (row >= M) continue;
            #pragma unroll
            for (int nt = 0; nt < 4; nt++) {
                int col = col0 + wn * 32 + nt * 8 + tig * 2;
                float v0 = acc[mt][nt][half * 2 + 0];
                float v1 = acc[mt][nt][half * 2 + 1];
                size_t o = (size_t)row * N + col;
                if (MODE == 1) {
                    v0 += bias[col]     + add[o];
                    v1 += bias[col + 1] + add[o + 1];
                } else if (MODE == 2) {
                    v0 = gelu_exact(v0 + bias[col]);
                    v1 = gelu_exact(v1 + bias[col + 1]);
                }
                *(float2*)&C[o] = make_float2(v0, v1);
            }
        }
    }
}

// ---------------- fused gather + conv-epilogue + LN + GELU (float4) --------
// 256 threads/node: 64 col-groups x 4 edge slots; LDG.128 gathers.
__global__ void __launch_bounds__(256) gcn_post(
    const float* __restrict__ hw, const float* __restrict__ pp,
    const int* __restrict__ rowptr, const int* __restrict__ esrc,
    const float* __restrict__ enorm, const float* __restrict__ dinv,
    const float* __restrict__ bcv, const float* __restrict__ bpv,
    const float* __restrict__ gv, const float* __restrict__ bev,
    float* __restrict__ skip_out, float* __restrict__ h_out) {
    int r = blockIdx.x;
    int tid = threadIdx.x;
    int g = tid & 63;       // column group (4 floats)
    int e = tid >> 6;       // edge slot 0..3
    int lane = tid & 31;
    int warp = tid >> 5;
    int beg = rowptr[r], end = rowptr[r + 1];

    float4 acc = make_float4(0.f, 0.f, 0.f, 0.f);
    for (int j = beg + e; j < end; j += 4) {
        int s = __ldg(&esrc[j]);          // uniform within warp -> broadcast
        float w = __ldg(&enorm[j]);
        const float4 v = *(const float4*)&hw[(size_t)s * 256 + g * 4];
        acc.x = fmaf(v.x, w, acc.x);
        acc.y = fmaf(v.y, w, acc.y);
        acc.z = fmaf(v.z, w, acc.z);
        acc.w = fmaf(v.w, w, acc.w);
    }
    __shared__ float4 sacc[256];
    sacc[tid] = acc;
    __syncthreads();

    float4 t = make_float4(0.f, 0.f, 0.f, 0.f);
    float partial = 0.f;
    size_t base = (size_t)r * 256 + g * 4;
    if (tid < 64) {
        float4 a0 = sacc[g], a1 = sacc[g + 64], a2 = sacc[g + 128], a3 = sacc[g + 192];
        float ax = a0.x + a1.x + a2.x + a3.x;
        float ay = a0.y + a1.y + a2.y + a3.y;
        float az = a0.z + a1.z + a2.z + a3.z;
        float aw = a0.w + a1.w + a2.w + a3.w;
        float di = dinv[r];
        float d2 = di * di;
        float4 hv = *(const float4*)&hw[base];
        float4 pv = *(const float4*)&pp[base];
        float4 bc4 = *(const float4*)&bcv[g * 4];
        float4 bp4 = *(const float4*)&bpv[g * 4];
        t.x = ax + d2 * hv.x + bc4.x + pv.x + bp4.x;
        t.y = ay + d2 * hv.y + bc4.y + pv.y + bp4.y;
        t.z = az + d2 * hv.z + bc4.z + pv.z + bp4.z;
        t.w = aw + d2 * hv.w + bc4.w + pv.w + bp4.w;
        *(float4*)&skip_out[base] = t;
        partial = t.x + t.y + t.z + t.w;
    }

    __shared__ float red[8];
    float s = partial;
    #pragma unroll
    for (int o = 16; o > 0; o >>= 1) s += __shfl_xor_sync(0xffffffffu, s, o);
    if (lane == 0) red[warp] = s;
    __syncthreads();
    float m = 0.f;
    #pragma unroll
    for (int i = 0; i < 8; i++) m += red[i];
    m *= (1.0f / 256.0f);
    __syncthreads();

    float vpart = 0.f;
    float dx = 0.f, dy = 0.f, dz = 0.f, dw = 0.f;
    if (tid < 64) {
        dx = t.x - m; dy = t.y - m; dz = t.z - m; dw = t.w - m;
        vpart = dx * dx + dy * dy + dz * dz + dw * dw;
    }
    float sv = vpart;
    #pragma unroll
    for (int o = 16; o > 0; o >>= 1) sv += __shfl_xor_sync(0xffffffffu, sv, o);
    if (lane == 0) red[warp] = sv;
    __syncthreads();
    float var = 0.f;
    #pragma unroll
    for (int i = 0; i < 8; i++) var += red[i];
    var *= (1.0f / 256.0f);

    if (tid < 64) {
        float rs = rsqrtf(var + 1e-5f);
        float4 g4 = *(const float4*)&gv[g * 4];
        float4 b4 = *(const float4*)&bev[g * 4];
        float4 y;
        y.x = gelu_exact(dx * rs * g4.x + b4.x);
        y.y = gelu_exact(dy * rs * g4.y + b4.y);
        y.z = gelu_exact(dz * rs * g4.z + b4.z);
        y.w = gelu_exact(dw * rs * g4.w + b4.w);
        *(float4*)&h_out[base] = y;
    }
}

// ---------------- log-softmax over 64 logits -------------------------------
__global__ void k_logsoftmax(const float* __restrict__ logits, const float* __restrict__ bf2,
                             float* __restrict__ out, int Nn) {
    int r = blockIdx.x * 8 + (threadIdx.x >> 5);
    int lane = threadIdx.x & 31;
    if (r >= Nn) return;
    float v0 = logits[(size_t)r * 64 + lane]      + bf2[lane];
    float v1 = logits[(size_t)r * 64 + 32 + lane] + bf2[32 + lane];
    float mx = fmaxf(v0, v1);
    #pragma unroll
    for (int o = 16; o > 0; o >>= 1) mx = fmaxf(mx, __shfl_xor_sync(0xffffffffu, mx, o));
    float s = expf(v0 - mx) + expf(v1 - mx);
    #pragma unroll
    for (int o = 16; o > 0; o >>= 1) s += __shfl_xor_sync(0xffffffffu, s, o);
    float ls = logf(s);
    out[(size_t)r * 64 + lane]      = v0 - mx - ls;
    out[(size_t)r * 64 + 32 + lane] = v1 - mx - ls;
}

// ---------------- launch ---------------------------------------------------
extern "C" void kernel_launch(void* const* d_in, const int* in_sizes, int n_in,
                              void* d_out, int out_size) {
    const float* x  = (const float*)d_in[0];
    const int*   ei = (const int*)d_in[1];
    int E  = in_sizes[1] / 2;
    int Nn = in_sizes[0] / 128;
    const int* src = ei;
    const int* dst = ei + E;

    const float* Wc[3] = {(const float*)d_in[2],  (const float*)d_in[8],  (const float*)d_in[14]};
    const float* bc[3] = {(const float*)d_in[3],  (const float*)d_in[9],  (const float*)d_in[15]};
    const float* Wp[3] = {(const float*)d_in[4],  (const float*)d_in[10], (const float*)d_in[16]};
    const float* bp[3] = {(const float*)d_in[5],  (const float*)d_in[11], (const float*)d_in[17]};
    const float* gg[3] = {(const float*)d_in[6],  (const float*)d_in[12], (const float*)d_in[18]};
    const float* be[3] = {(const float*)d_in[7],  (const float*)d_in[13], (const float*)d_in[19]};
    const float* W_in = (const float*)d_in[20];
    const float* b_in = (const float*)d_in[21];
    const float* Wf1  = (const float*)d_in[22];
    const float* bf1  = (const float*)d_in[23];
    const float* Wf2  = (const float*)d_in[24];
    const float* bf2  = (const float*)d_in[25];
    float* out = (float*)d_out;

    cudaFuncSetAttribute(sgemm_tc<0>, cudaFuncAttributeMaxDynamicSharedMemorySize, SMEM_BYTES);
    cudaFuncSetAttribute(sgemm_tc<1>, cudaFuncAttributeMaxDynamicSharedMemorySize, SMEM_BYTES);
    cudaFuncSetAttribute(sgemm_tc<2>, cudaFuncAttributeMaxDynamicSharedMemorySize, SMEM_BYTES);

    float *pH, *pSkip, *pHw, *pP, *pF1, *pLog, *pDinv, *pEn, *pWt;
    int *pDegi, *pRp, *pCur, *pEs;
    cudaGetSymbolAddress((void**)&pH,    g_h);
    cudaGetSymbolAddress((void**)&pSkip, g_skip);
    cudaGetSymbolAddress((void**)&pHw,   g_hw);
    cudaGetSymbolAddress((void**)&pP,    g_p);
    cudaGetSymbolAddress((void**)&pF1,   g_f1);
    cudaGetSymbolAddress((void**)&pLog,  g_logits);
    cudaGetSymbolAddress((void**)&pDinv, g_dinv);
    cudaGetSymbolAddress((void**)&pDegi, g_degi);
    cudaGetSymbolAddress((void**)&pRp,   g_rowptr);
    cudaGetSymbolAddress((void**)&pCur,  g_cursor);
    cudaGetSymbolAddress((void**)&pEs,   g_esrc);
    cudaGetSymbolAddress((void**)&pEn,   g_enorm);
    cudaGetSymbolAddress((void**)&pWt,   g_wt);

    // transposed-weight offsets (floats)
    // order: Wc0,Wp0,Wc1,Wp1,Wc2,Wp2,W_in,Wf1,Wf2
    TransArgs ta;
    const float* Ws[9] = {Wc[0], Wp[0], Wc[1], Wp[1], Wc[2], Wp[2], W_in, Wf1, Wf2};
    int Ks[9] = {128, 128, 256, 256, 256, 256, 128, 256, 512};
    int Nss[9] = {256, 256, 256, 256, 256, 256, 256, 512, 64};
    long long woff[9];
    long long run = 0;
    for (int i = 0; i < 9; i++) {
        ta.W[i] = Ws[i];
        ta.K[i] = Ks[i];
        ta.N[i] = Nss[i];
        ta.woff[i] = run;
        woff[i] = run;
        run += (long long)Ks[i] * Nss[i];
    }

    // --- preprocessing (5 launches before first GEMM) ---
    k_transpose_all<<<dim3(16, 16, 9), dim3(32, 8)>>>(ta, pWt);
    cudaMemsetAsync(pDegi, 0, (size_t)Nn * sizeof(int), 0);
    k_count<<<(E + 255) / 256, 256>>>(pDegi, dst, E);
    k_scan_all<<<1, 1024>>>(pDegi, pDinv, pRp, pCur, Nn, E);
    k_bucket<<<(E + 255) / 256, 256>>>(src, dst, pDinv, pCur, pEs, pEn, E);

    // --- 3 GCN layers ---
    const float* h    = x;
    const float* skip = x;
    int Kin = 128;
    int gy = (Nn + 127) / 128;
    for (int l = 0; l < 3; l++) {
        sgemm_tc<0><<<dim3(4, gy), 256, SMEM_BYTES>>>(h,    pWt + woff[2 * l],     pHw, Nn, Kin, 256, nullptr, nullptr);
        sgemm_tc<0><<<dim3(4, gy), 256, SMEM_BYTES>>>(skip, pWt + woff[2 * l + 1], pP,  Nn, Kin, 256, nullptr, nullptr);
        gcn_post<<<Nn, 256>>>(pHw, pP, pRp, pEs, pEn, pDinv,
                              bc[l], bp[l], gg[l], be[l], pSkip, pH);
        h = pH; skip = pSkip; Kin = 256;
    }

    // --- long residual (fused epilogue) + MLP head ---
    sgemm_tc<1><<<dim3(4, gy), 256, SMEM_BYTES>>>(x, pWt + woff[6], pHw, Nn, 128, 256, b_in, pH);
    sgemm_tc<2><<<dim3(8, gy), 256, SMEM_BYTES>>>(pHw, pWt + woff[7], pF1, Nn, 256, 512, bf1, nullptr);
    sgemm_tc<0><<<dim3(1, gy), 256, SMEM_BYTES>>>(pF1, pWt + woff[8], pLog, Nn, 512, 64, nullptr, nullptr);
    k_logsoftmax<<<(Nn + 7) / 8, 256>>>(pLog, bf2, out, Nn);
}

// round 10
// speedup vs baseline: 1.0556x; 1.0556x over previous
#include <cuda_runtime.h>
#include <math.h>
#include <stdint.h>

#define MAXN 50048
#define MAXE 800000

// ---------------- scratch (device globals; no allocation allowed) ----------
__device__ __align__(128) float g_h[MAXN * 256];
__device__ __align__(128) float g_skip[MAXN * 256];
__device__ __align__(128) float g_hw[MAXN * 256];
__device__ __align__(128) float g_p[MAXN * 256];
__device__ __align__(128) float g_f1[MAXN * 512];
__device__ __align__(128) float g_logits[MAXN * 64];
__device__ __align__(128) float g_dinv[MAXN];
__device__ __align__(128) int   g_degi[MAXN];
__device__ __align__(128) int   g_rowptr[MAXN + 1];
__device__ __align__(128) int   g_cursor[MAXN];
__device__ __align__(128) int   g_esrc[MAXE];
__device__ __align__(128) float g_enorm[MAXE];
__device__ __align__(128) float g_wt[524288];   // all transposed weights (2 MB)

// ---------------- helpers --------------------------------------------------
__device__ __forceinline__ float gelu_exact(float x) {
    return 0.5f * x * (1.0f + erff(x * 0.70710678118654752440f));
}
__device__ __forceinline__ void mma_tf32(float* c, const uint32_t* a, const uint32_t* b) {
    asm("mma.sync.aligned.m16n8k8.row.col.f32.tf32.tf32.f32 "
        "{%0,%1,%2,%3},{%4,%5,%6,%7},{%8,%9},{%0,%1,%2,%3};"
        : "+f"(c[0]), "+f"(c[1]), "+f"(c[2]), "+f"(c[3])
        : "r"(a[0]), "r"(a[1]), "r"(a[2]), "r"(a[3]), "r"(b[0]), "r"(b[1]));
}
__device__ __forceinline__ void ldsm_x4(uint32_t* r, uint32_t saddr) {
    asm volatile("ldmatrix.sync.aligned.m8n8.x4.shared.b16 {%0,%1,%2,%3}, [%4];"
                 : "=r"(r[0]), "=r"(r[1]), "=r"(r[2]), "=r"(r[3]) : "r"(saddr));
}
__device__ __forceinline__ void ldsm_x2(uint32_t* r, uint32_t saddr) {
    asm volatile("ldmatrix.sync.aligned.m8n8.x2.shared.b16 {%0,%1}, [%2];"
                 : "=r"(r[0]), "=r"(r[1]) : "r"(saddr));
}
__device__ __forceinline__ void cp16(void* dst, const void* src, int bytes) {
    uint32_t d = (uint32_t)__cvta_generic_to_shared(dst);
    asm volatile("cp.async.cg.shared.global [%0], [%1], 16, %2;"
                 :: "r"(d), "l"(src), "r"(bytes));
}
__device__ __forceinline__ void cp_commit() { asm volatile("cp.async.commit_group;"); }
template <int N>
__device__ __forceinline__ void cp_wait() { asm volatile("cp.async.wait_group %0;" :: "n"(N)); }

// ---------------- batched weight transpose + degi zero ---------------------
struct TransArgs {
    const float* W[9];
    long long    woff[9];
    int K[9];
    int N[9];
};
__global__ void k_transpose_all(TransArgs a, float* wt, int* degi, int n) {
    int m = blockIdx.z;
    if (m == 9) {   // zero degree counters (replaces cudaMemsetAsync workload)
        int id = (blockIdx.y * gridDim.x + blockIdx.x) * 256 + threadIdx.y * 32 + threadIdx.x;
        if (id < n) degi[id] = 0;
        return;
    }
    __shared__ float tile[32][33];
    int K = a.K[m], N = a.N[m];
    int k0 = blockIdx.x * 32, n0 = blockIdx.y * 32;
    if (k0 >= K || n0 >= N) return;
    const float* W = a.W[m];
    float* Wt = wt + a.woff[m];
    for (int i = threadIdx.y; i < 32; i += 8)
        tile[i][threadIdx.x] = W[(size_t)(k0 + i) * N + n0 + threadIdx.x];
    __syncthreads();
    for (int i = threadIdx.y; i < 32; i += 8)
        Wt[(size_t)(n0 + i) * K + k0 + threadIdx.x] = tile[threadIdx.x][i];
}

// ---------------- preprocessing --------------------------------------------
__global__ void k_count(int* deg, const int* __restrict__ dst, int e) {
    int i = blockIdx.x * blockDim.x + threadIdx.x;
    if (i < e) atomicAdd(&deg[dst[i]], 1);
}
__global__ void __launch_bounds__(1024) k_scan_all(
    const int* __restrict__ deg, float* __restrict__ dinv,
    int* __restrict__ rowptr, int* __restrict__ cursor, int n, int e) {
    __shared__ int sh[1024];
    int t = threadIdx.x;
    int per = (n + 1023) >> 10;
    int lo = t * per, hi = min(lo + per, n);
    int sum = 0;
    for (int i = lo; i < hi; i++) sum += deg[i];
    sh[t] = sum;
    __syncthreads();
    for (int o = 1; o < 1024; o <<= 1) {
        int u = (t >= o) ? sh[t - o] : 0;
        __syncthreads();
        sh[t] += u;
        __syncthreads();
    }
    int off = sh[t] - sum;
    for (int i = lo; i < hi; i++) {
        int d = deg[i];
        rowptr[i] = off;
        cursor[i] = off;
        dinv[i] = rsqrtf((float)d + 1.0f);
        off += d;
    }
    if (t == 0) rowptr[n] = e;
}
__global__ void k_bucket(const int* __restrict__ src, const int* __restrict__ dst,
                         const float* __restrict__ dinv, int* __restrict__ cursor,
                         int* __restrict__ esrc, float* __restrict__ enorm, int e) {
    int i = blockIdx.x * blockDim.x + threadIdx.x;
    if (i < e) {
        int s = src[i], d = dst[i];
        int pos = atomicAdd(&cursor[d], 1);
        esrc[pos] = s;
        enorm[pos] = dinv[s] * dinv[d];
    }
}

// ---------------- BIG TF32 GEMM: 128x128 tile, 2-stage, ldmatrix -----------
// C[M,N] = A[M,K] @ Bt^T, Bt is [N][K] k-contiguous. N%128==0, K%32==0.
// 8 warps: 4 in M x 2 in N, warp tile 32x64. 2 CTAs/SM.
// MODE: 0 raw, 1 +bias+addmat, 2 gelu(x+bias)
#define BPITCH 36
#define BIG_A_STAGE (128 * BPITCH)
#define BIG_B_STAGE (128 * BPITCH)
#define BIG_STAGE   (BIG_A_STAGE + BIG_B_STAGE)
#define BIG_SMEM_BYTES (2 * BIG_STAGE * 4)   // 73728

template <int MODE>
__global__ void __launch_bounds__(256, 2) sgemm_big(
    const float* __restrict__ A, const float* __restrict__ Bt, float* __restrict__ C,
    int M, int K, int N, const float* __restrict__ bias, const float* __restrict__ add) {
    extern __shared__ float smem[];
    const uint32_t smem_u32 = (uint32_t)__cvta_generic_to_shared(smem);

    const int tid  = threadIdx.x;
    const int lane = tid & 31;
    const int wid  = tid >> 5;
    const int wm = wid & 3, wn = wid >> 2;
    const int gid = lane >> 2, tig = lane & 3;
    const int row0 = blockIdx.y * 128;
    const int col0 = blockIdx.x * 128;

    // loaders: A = 128 rows x 8 chunks, B = 128 rows x 8 chunks; 4 each/thread
    const int lr[4] = {(tid + 0) >> 3, (tid + 256) >> 3, (tid + 512) >> 3, (tid + 768) >> 3};
    const int lk = (tid & 7) * 4;

    const int k_tiles = K >> 5;

    auto load_stage = [&](int s, int k0) {
        float* as = smem + s * BIG_STAGE;
        float* bs = as + BIG_A_STAGE;
        #pragma unroll
        for (int i = 0; i < 4; i++) {
            int row = lr[i];
            int grow = row0 + row;
            int ok = (grow < M) ? 16 : 0;
            if (!ok) grow = M - 1;
            cp16(&as[row * BPITCH + lk], &A[(size_t)grow * K + k0 + lk], ok);
        }
        #pragma unroll
        for (int i = 0; i < 4; i++) {
            int n = lr[i];
            cp16(&bs[n * BPITCH + lk], &Bt[(size_t)(col0 + n) * K + k0 + lk], 16);
        }
    };

    // ldmatrix lane offsets (floats*4 = bytes)
    const int a_i = lane & 7, a_t = lane >> 3;
    const uint32_t a_off = ((uint32_t)((wm * 32 + a_i + ((a_t & 1) << 3)) * BPITCH
                                       + ((a_t >> 1) << 2))) * 4u;
    const int b_i = lane & 7, b_t = (lane >> 3) & 1;
    const uint32_t b_off = ((uint32_t)((wn * 64 + b_i) * BPITCH + (b_t << 2))) * 4u;

    float acc[2][8][4];
    #pragma unroll
    for (int i = 0; i < 2; i++)
        #pragma unroll
        for (int j = 0; j < 8; j++)
            #pragma unroll
            for (int k = 0; k < 4; k++) acc[i][j][k] = 0.0f;

    load_stage(0, 0);
    cp_commit();

    for (int t = 0; t < k_tiles; t++) {
        cp_wait<0>();
        __syncthreads();
        const int st = t & 1;
        if (t + 1 < k_tiles) {
            load_stage((t + 1) & 1, (t + 1) * 32);
        }
        cp_commit();

        const uint32_t as_base = smem_u32 + (uint32_t)(st * BIG_STAGE) * 4u;
        const uint32_t bs_base = as_base + (uint32_t)BIG_A_STAGE * 4u;

        #pragma unroll
        for (int kb = 0; kb < 32; kb += 8) {
            uint32_t af[2][4], bf[8][2];
            #pragma unroll
            for (int mt = 0; mt < 2; mt++)
                ldsm_x4(af[mt], as_base + a_off + (uint32_t)(mt * 16 * BPITCH + kb) * 4u);
            #pragma unroll
            for (int nt = 0; nt < 8; nt++)
                ldsm_x2(bf[nt], bs_base + b_off + (uint32_t)(nt * 8 * BPITCH + kb) * 4u);
            #pragma unroll
            for (int mt = 0; mt < 2; mt++)
                #pragma unroll
                for (int nt = 0; nt < 8; nt++)
                    mma_tf32(acc[mt][nt], af[mt], bf[nt]);
        }
    }

    #pragma unroll
    for (int mt = 0; mt < 2; mt++) {
        #pragma unroll
        for (int half = 0; half < 2; half++) {
            int row = row0 + wm * 32 + mt * 16 + gid + half * 8;
            if (row >= M) continue;
            #pragma unroll
            for (int nt = 0; nt < 8; nt++) {
                int col = col0 + wn * 64 + nt * 8 + tig * 2;
                float v0 = acc[mt][nt][half * 2 + 0];
                float v1 = acc[mt][nt][half * 2 + 1];
                size_t o = (size_t)row * N + col;
                if (MODE == 1) {
                    v0 += bias[col]     + add[o];
                    v1 += bias[col + 1] + add[o + 1];
                } else if (MODE == 2) {
                    v0 = gelu_exact(v0 + bias[col]);
                    v1 = gelu_exact(v1 + bias[col + 1]);
                }
                *(float2*)&C[o] = make_float2(v0, v1);
            }
        }
    }
}

// ---------------- SMALL TF32 GEMM (N=64 logits), 3-stage, ldmatrix ---------
#define S_STAGES 3
#define S_A_STAGE (128 * BPITCH)
#define S_B_STAGE (64 * BPITCH)
#define S_SMEM_BYTES (S_STAGES * (S_A_STAGE + S_B_STAGE) * 4)   // 82944

__global__ void __launch_bounds__(256) sgemm_small(
    const float* __restrict__ A, const float* __restrict__ Bt, float* __restrict__ C,
    int M, int K, int N) {
    extern __shared__ float smem[];
    const uint32_t smem_u32 = (uint32_t)__cvta_generic_to_shared(smem);

    const int tid  = threadIdx.x;
    const int lane = tid & 31;
    const int wid  = tid >> 5;
    const int wm = wid & 3, wn = wid >> 2;
    const int gid = lane >> 2, tig = lane & 3;
    const int row0 = blockIdx.y * 128;
    const int col0 = 0;

    const int ar[4] = {(tid + 0) >> 3, (tid + 256) >> 3, (tid + 512) >> 3, (tid + 768) >> 3};
    const int ak = (tid & 7) * 4;
    const int bn[2] = {(tid + 0) >> 3, (tid + 256) >> 3};
    const int bk = (tid & 7) * 4;

    const int k_tiles = K >> 5;

    auto load_stage = [&](int s, int k0) {
        float* as = smem + s * S_A_STAGE;
        float* bs = smem + S_STAGES * S_A_STAGE + s * S_B_STAGE;
        #pragma unroll
        for (int i = 0; i < 4; i++) {
            int row = ar[i];
            int grow = row0 + row;
            int ok = (grow < M) ? 16 : 0;
            if (!ok) grow = M - 1;
            cp16(&as[row * BPITCH + ak], &A[(size_t)grow * K + k0 + ak], ok);
        }
        #pragma unroll
        for (int i = 0; i < 2; i++) {
            int n = bn[i];
            cp16(&bs[n * BPITCH + bk], &Bt[(size_t)(col0 + n) * K + k0 + bk], 16);
        }
    };

    const int a_i = lane & 7, a_t = lane >> 3;
    const uint32_t a_off = ((uint32_t)((wm * 32 + a_i + ((a_t & 1) << 3)) * BPITCH
                                       + ((a_t >> 1) << 2))) * 4u;
    const int b_i = lane & 7, b_t = (lane >> 3) & 1;
    const uint32_t b_off = ((uint32_t)((wn * 32 + b_i) * BPITCH + (b_t << 2))) * 4u;

    float acc[2][4][4];
    #pragma unroll
    for (int i = 0; i < 2; i++)
        #pragma unroll
        for (int j = 0; j < 4; j++)
            #pragma unroll
            for (int k = 0; k < 4; k++) acc[i][j][k] = 0.0f;

    #pragma unroll
    for (int s = 0; s < S_STAGES - 1; s++) {
        if (s < k_tiles) load_stage(s, s * 32);
        cp_commit();
    }

    for (int t = 0; t < k_tiles; t++) {
        cp_wait<S_STAGES - 2>();
        __syncthreads();
        const int st = t % S_STAGES;
        const uint32_t as_base = smem_u32 + (uint32_t)(st * S_A_STAGE) * 4u;
        const uint32_t bs_base = smem_u32 + (uint32_t)(S_STAGES * S_A_STAGE + st * S_B_STAGE) * 4u;

        #pragma unroll
        for (int kb = 0; kb < 32; kb += 8) {
            uint32_t af[2][4], bf[4][2];
            #pragma unroll
            for (int mt = 0; mt < 2; mt++)
                ldsm_x4(af[mt], as_base + a_off + (uint32_t)(mt * 16 * BPITCH + kb) * 4u);
            #pragma unroll
            for (int nt = 0; nt < 4; nt++)
                ldsm_x2(bf[nt], bs_base + b_off + (uint32_t)(nt * 8 * BPITCH + kb) * 4u);
            #pragma unroll
            for (int mt = 0; mt < 2; mt++)
                #pragma unroll
                for (int nt = 0; nt < 4; nt++)
                    mma_tf32(acc[mt][nt], af[mt], bf[nt]);
        }

        int nt2 = t + S_STAGES - 1;
        if (nt2 < k_tiles) load_stage(nt2 % S_STAGES, nt2 * 32);
        cp_commit();
    }

    #pragma unroll
    for (int mt = 0; mt < 2; mt++) {
        #pragma unroll
        for (int half = 0; half < 2; half++) {
            int row = row0 + wm * 32 + mt * 16 + gid + half * 8;
            if (row >= M) continue;
            #pragma unroll
            for (int nt = 0; nt < 4; nt++) {
                int col = col0 + wn * 32 + nt * 8 + tig * 2;
                size_t o = (size_t)row * N + col;
                *(float2*)&C[o] = make_float2(acc[mt][nt][half * 2 + 0],
                                              acc[mt][nt][half * 2 + 1]);
            }
        }
    }
}

// ---------------- fused gather + conv-epilogue + LN + GELU (float4) --------
__global__ void __launch_bounds__(256) gcn_post(
    const float* __restrict__ hw, const float* __restrict__ pp,
    const int* __restrict__ rowptr, const int* __restrict__ esrc,
    const float* __restrict__ enorm, const float* __restrict__ dinv,
    const float* __restrict__ bcv, const float* __restrict__ bpv,
    const float* __restrict__ gv, const float* __restrict__ bev,
    float* __restrict__ skip_out, float* __restrict__ h_out) {
    int r = blockIdx.x;
    int tid = threadIdx.x;
    int g = tid & 63;
    int e = tid >> 6;
    int lane = tid & 31;
    int warp = tid >> 5;
    int beg = rowptr[r], end = rowptr[r + 1];

    float4 acc = make_float4(0.f, 0.f, 0.f, 0.f);
    for (int j = beg + e; j < end; j += 4) {
        int s = __ldg(&esrc[j]);
        float w = __ldg(&enorm[j]);
        const float4 v = *(const float4*)&hw[(size_t)s * 256 + g * 4];
        acc.x = fmaf(v.x, w, acc.x);
        acc.y = fmaf(v.y, w, acc.y);
        acc.z = fmaf(v.z, w, acc.z);
        acc.w = fmaf(v.w, w, acc.w);
    }
    __shared__ float4 sacc[256];
    sacc[tid] = acc;
    __syncthreads();

    float4 t = make_float4(0.f, 0.f, 0.f, 0.f);
    float partial = 0.f;
    size_t base = (size_t)r * 256 + g * 4;
    if (tid < 64) {
        float4 a0 = sacc[g], a1 = sacc[g + 64], a2 = sacc[g + 128], a3 = sacc[g + 192];
        float ax = a0.x + a1.x + a2.x + a3.x;
        float ay = a0.y + a1.y + a2.y + a3.y;
        float az = a0.z + a1.z + a2.z + a3.z;
        float aw = a0.w + a1.w + a2.w + a3.w;
        float di = dinv[r];
        float d2 = di * di;
        float4 hv = *(const float4*)&hw[base];
        float4 pv = *(const float4*)&pp[base];
        float4 bc4 = *(const float4*)&bcv[g * 4];
        float4 bp4 = *(const float4*)&bpv[g * 4];
        t.x = ax + d2 * hv.x + bc4.x + pv.x + bp4.x;
        t.y = ay + d2 * hv.y + bc4.y + pv.y + bp4.y;
        t.z = az + d2 * hv.z + bc4.z + pv.z + bp4.z;
        t.w = aw + d2 * hv.w + bc4.w + pv.w + bp4.w;
        *(float4*)&skip_out[base] = t;
        partial = t.x + t.y + t.z + t.w;
    }

    __shared__ float red[8];
    float s = partial;
    #pragma unroll
    for (int o = 16; o > 0; o >>= 1) s += __shfl_xor_sync(0xffffffffu, s, o);
    if (lane == 0) red[warp] = s;
    __syncthreads();
    float m = 0.f;
    #pragma unroll
    for (int i = 0; i < 8; i++) m += red[i];
    m *= (1.0f / 256.0f);
    __syncthreads();

    float vpart = 0.f;
    float dx = 0.f, dy = 0.f, dz = 0.f, dw = 0.f;
    if (tid < 64) {
        dx = t.x - m; dy = t.y - m; dz = t.z - m; dw = t.w - m;
        vpart = dx * dx + dy * dy + dz * dz + dw * dw;
    }
    float sv = vpart;
    #pragma unroll
    for (int o = 16; o > 0; o >>= 1) sv += __shfl_xor_sync(0xffffffffu, sv, o);
    if (lane == 0) red[warp] = sv;
    __syncthreads();
    float var = 0.f;
    #pragma unroll
    for (int i = 0; i < 8; i++) var += red[i];
    var *= (1.0f / 256.0f);

    if (tid < 64) {
        float rs = rsqrtf(var + 1e-5f);
        float4 g4 = *(const float4*)&gv[g * 4];
        float4 b4 = *(const float4*)&bev[g * 4];
        float4 y;
        y.x = gelu_exact(dx * rs * g4.x + b4.x);
        y.y = gelu_exact(dy * rs * g4.y + b4.y);
        y.z = gelu_exact(dz * rs * g4.z + b4.z);
        y.w = gelu_exact(dw * rs * g4.w + b4.w);
        *(float4*)&h_out[base] = y;
    }
}

// ---------------- log-softmax over 64 logits -------------------------------
__global__ void k_logsoftmax(const float* __restrict__ logits, const float* __restrict__ bf2,
                             float* __restrict__ out, int Nn) {
    int r = blockIdx.x * 8 + (threadIdx.x >> 5);
    int lane = threadIdx.x & 31;
    if (r >= Nn) return;
    float v0 = logits[(size_t)r * 64 + lane]      + bf2[lane];
    float v1 = logits[(size_t)r * 64 + 32 + lane] + bf2[32 + lane];
    float mx = fmaxf(v0, v1);
    #pragma unroll
    for (int o = 16; o > 0; o >>= 1) mx = fmaxf(mx, __shfl_xor_sync(0xffffffffu, mx, o));
    float s = expf(v0 - mx) + expf(v1 - mx);
    #pragma unroll
    for (int o = 16; o > 0; o >>= 1) s += __shfl_xor_sync(0xffffffffu, s, o);
    float ls = logf(s);
    out[(size_t)r * 64 + lane]      = v0 - mx - ls;
    out[(size_t)r * 64 + 32 + lane] = v1 - mx - ls;
}

// ---------------- launch ---------------------------------------------------
extern "C" void kernel_launch(void* const* d_in, const int* in_sizes, int n_in,
                              void* d_out, int out_size) {
    const float* x  = (const float*)d_in[0];
    const int*   ei = (const int*)d_in[1];
    int E  = in_sizes[1] / 2;
    int Nn = in_sizes[0] / 128;
    const int* src = ei;
    const int* dst = ei + E;

    const float* Wc[3] = {(const float*)d_in[2],  (const float*)d_in[8],  (const float*)d_in[14]};
    const float* bc[3] = {(const float*)d_in[3],  (const float*)d_in[9],  (const float*)d_in[15]};
    const float* Wp[3] = {(const float*)d_in[4],  (const float*)d_in[10], (const float*)d_in[16]};
    const float* bp[3] = {(const float*)d_in[5],  (const float*)d_in[11], (const float*)d_in[17]};
    const float* gg[3] = {(const float*)d_in[6],  (const float*)d_in[12], (const float*)d_in[18]};
    const float* be[3] = {(const float*)d_in[7],  (const float*)d_in[13], (const float*)d_in[19]};
    const float* W_in = (const float*)d_in[20];
    const float* b_in = (const float*)d_in[21];
    const float* Wf1  = (const float*)d_in[22];
    const float* bf1  = (const float*)d_in[23];
    const float* Wf2  = (const float*)d_in[24];
    const float* bf2  = (const float*)d_in[25];
    float* out = (float*)d_out;

    cudaFuncSetAttribute(sgemm_big<0>, cudaFuncAttributeMaxDynamicSharedMemorySize, BIG_SMEM_BYTES);
    cudaFuncSetAttribute(sgemm_big<1>, cudaFuncAttributeMaxDynamicSharedMemorySize, BIG_SMEM_BYTES);
    cudaFuncSetAttribute(sgemm_big<2>, cudaFuncAttributeMaxDynamicSharedMemorySize, BIG_SMEM_BYTES);
    cudaFuncSetAttribute(sgemm_small,  cudaFuncAttributeMaxDynamicSharedMemorySize, S_SMEM_BYTES);

    float *pH, *pSkip, *pHw, *pP, *pF1, *pLog, *pDinv, *pEn, *pWt;
    int *pDegi, *pRp, *pCur, *pEs;
    cudaGetSymbolAddress((void**)&pH,    g_h);
    cudaGetSymbolAddress((void**)&pSkip, g_skip);
    cudaGetSymbolAddress((void**)&pHw,   g_hw);
    cudaGetSymbolAddress((void**)&pP,    g_p);
    cudaGetSymbolAddress((void**)&pF1,   g_f1);
    cudaGetSymbolAddress((void**)&pLog,  g_logits);
    cudaGetSymbolAddress((void**)&pDinv, g_dinv);
    cudaGetSymbolAddress((void**)&pDegi, g_degi);
    cudaGetSymbolAddress((void**)&pRp,   g_rowptr);
    cudaGetSymbolAddress((void**)&pCur,  g_cursor);
    cudaGetSymbolAddress((void**)&pEs,   g_esrc);
    cudaGetSymbolAddress((void**)&pEn,   g_enorm);
    cudaGetSymbolAddress((void**)&pWt,   g_wt);

    TransArgs ta;
    const float* Ws[9] = {Wc[0], Wp[0], Wc[1], Wp[1], Wc[2], Wp[2], W_in, Wf1, Wf2};
    int Ks[9] = {128, 128, 256, 256, 256, 256, 128, 256, 512};
    int Nss[9] = {256, 256, 256, 256, 256, 256, 256, 512, 64};
    long long woff[9];
    long long run = 0;
    for (int i = 0; i < 9; i++) {
        ta.W[i] = Ws[i];
        ta.K[i] = Ks[i];
        ta.N[i] = Nss[i];
        ta.woff[i] = run;
        woff[i] = run;
        run += (long long)Ks[i] * Nss[i];
    }

    // --- preprocessing: 4 workloads (first GEMM is workload #5 for ncu -s 5) ---
    k_transpose_all<<<dim3(16, 16, 10), dim3(32, 8)>>>(ta, pWt, pDegi, Nn);
    k_count<<<(E + 255) / 256, 256>>>(pDegi, dst, E);
    k_scan_all<<<1, 1024>>>(pDegi, pDinv, pRp, pCur, Nn, E);
    k_bucket<<<(E + 255) / 256, 256>>>(src, dst, pDinv, pCur, pEs, pEn, E);

    // --- 3 GCN layers ---
    const float* h    = x;
    const float* skip = x;
    int Kin = 128;
    int gy = (Nn + 127) / 128;
    for (int l = 0; l < 3; l++) {
        sgemm_big<0><<<dim3(2, gy), 256, BIG_SMEM_BYTES>>>(h,    pWt + woff[2 * l],     pHw, Nn, Kin, 256, nullptr, nullptr);
        sgemm_big<0><<<dim3(2, gy), 256, BIG_SMEM_BYTES>>>(skip, pWt + woff[2 * l + 1], pP,  Nn, Kin, 256, nullptr, nullptr);
        gcn_post<<<Nn, 256>>>(pHw, pP, pRp, pEs, pEn, pDinv,
                              bc[l], bp[l], gg[l], be[l], pSkip, pH);
        h = pH; skip = pSkip; Kin = 256;
    }

    // --- long residual (fused epilogue) + MLP head ---
    sgemm_big<1><<<dim3(2, gy), 256, BIG_SMEM_BYTES>>>(x, pWt + woff[6], pHw, Nn, 128, 256, b_in, pH);
    sgemm_big<2><<<dim3(4, gy), 256, BIG_SMEM_BYTES>>>(pHw, pWt + woff[7], pF1, Nn, 256, 512, bf1, nullptr);
    sgemm_small<<<dim3(1, gy), 256, S_SMEM_BYTES>>>(pF1, pWt + woff[8], pLog, Nn, 512, 64);
    k_logsoftmax<<<(Nn + 7) / 8, 256>>>(pLog, bf2, out, Nn);
}